// round 9
// baseline (speedup 1.0000x reference)
#include <cuda_runtime.h>
#include <cuda_bf16.h>
#include <cstdint>

// Problem constants (from reference): N=50000, F=128, E=800000, C=2
#define NMAX 50000

// Scratch projections: pu[n] = x[n] @ W_edge[:, :F].T  (4 floats)
//                      pv[n] = x[n] @ W_edge[:, F:].T  (4 floats)
__device__ float4 g_pu[NMAX];
__device__ float4 g_pv[NMAX];

// ---------------------------------------------------------------------------
// Kernel 1: one warp per node. Single coalesced read of x[n] (128 floats),
// 10 dot products (2 node potentials + 8 edge projections), warp reduce.
// ---------------------------------------------------------------------------
__global__ void crf_node_proj_kernel(const float* __restrict__ x,
                                     const float* __restrict__ W_node,
                                     const float* __restrict__ b_node,
                                     const float* __restrict__ W_edge,
                                     float* __restrict__ node_out,
                                     int N) {
    // sW rows: 0-1 = W_node[2][128]
    //          2-5 = W_edge[c][0:128]   (pu weights)
    //          6-9 = W_edge[c][128:256] (pv weights)
    __shared__ float4 sW[10][32];
    __shared__ float  sb[2];

    int tid = threadIdx.x;
    for (int i = tid; i < 320; i += blockDim.x) {
        int r = i >> 5, l = i & 31;
        float4 w;
        if (r < 2)       w = reinterpret_cast<const float4*>(W_node)[r * 32 + l];
        else if (r < 6)  w = reinterpret_cast<const float4*>(W_edge)[(r - 2) * 64 + l];
        else             w = reinterpret_cast<const float4*>(W_edge)[(r - 6) * 64 + 32 + l];
        sW[r][l] = w;
    }
    if (tid < 2) sb[tid] = b_node[tid];
    __syncthreads();

    int lane = tid & 31;
    int warp = tid >> 5;
    int wpb  = blockDim.x >> 5;

    for (int n = blockIdx.x * wpb + warp; n < N; n += gridDim.x * wpb) {
        float4 xv = reinterpret_cast<const float4*>(x)[n * 32 + lane];
        float acc[10];
#pragma unroll
        for (int r = 0; r < 10; r++) {
            float4 w = sW[r][lane];
            acc[r] = xv.x * w.x + xv.y * w.y + xv.z * w.z + xv.w * w.w;
        }
#pragma unroll
        for (int r = 0; r < 10; r++) {
#pragma unroll
            for (int off = 16; off > 0; off >>= 1)
                acc[r] += __shfl_xor_sync(0xffffffffu, acc[r], off);
        }
        if (lane == 0) {
            node_out[n * 2 + 0] = acc[0] + sb[0];
            node_out[n * 2 + 1] = acc[1] + sb[1];
            g_pu[n] = make_float4(acc[2], acc[3], acc[4], acc[5]);
            g_pv[n] = make_float4(acc[6], acc[7], acc[8], acc[9]);
        }
    }
}

// ---------------------------------------------------------------------------
// Kernel 2: one thread per edge. edge_index is INT32 (JAX downcasts int64
// without x64 mode). Two random float4 gathers from the 1.6 MB L2-resident
// projection tables, one coalesced float4 store.
// ---------------------------------------------------------------------------
__global__ void crf_edge_kernel(const int* __restrict__ ei,
                                const float* __restrict__ b_edge,
                                float* __restrict__ edge_out,
                                int E) {
    int e = blockIdx.x * blockDim.x + threadIdx.x;
    if (e >= E) return;
    float4 be = *reinterpret_cast<const float4*>(b_edge);
    int src = __ldg(&ei[e]);
    int dst = __ldg(&ei[E + e]);
    float4 a = g_pu[src];
    float4 b = g_pv[dst];
    reinterpret_cast<float4*>(edge_out)[e] =
        make_float4(a.x + b.x + be.x, a.y + b.y + be.y,
                    a.z + b.z + be.z, a.w + b.w + be.w);
}

// ---------------------------------------------------------------------------
// Launch
// ---------------------------------------------------------------------------
extern "C" void kernel_launch(void* const* d_in, const int* in_sizes, int n_in,
                              void* d_out, int out_size) {
    const float* x      = (const float*)d_in[0];  // [N, 128]
    const int*   ei     = (const int*)d_in[1];    // [2, E] int32 (JAX no-x64)
    const float* W_node = (const float*)d_in[2];  // [2, 128]
    const float* b_node = (const float*)d_in[3];  // [2]
    const float* W_edge = (const float*)d_in[4];  // [4, 256]
    const float* b_edge = (const float*)d_in[5];  // [4]

    int N = in_sizes[0] / 128;
    int E = in_sizes[1] / 2;

    float* node_out = (float*)d_out;           // [N, 2]
    float* edge_out = (float*)d_out + N * 2;   // [E, 4], 16B-aligned

    // Kernel 1: 256 threads = 8 warps/block, one warp per node
    int wpb = 8;
    int grid1 = (N + wpb - 1) / wpb;
    crf_node_proj_kernel<<<grid1, 256>>>(x, W_node, b_node, W_edge, node_out, N);

    // Kernel 2: one thread per edge
    int grid2 = (E + 255) / 256;
    crf_edge_kernel<<<grid2, 256>>>(ei, b_edge, edge_out, E);
}